// round 11
// baseline (speedup 1.0000x reference)
#include <cuda_runtime.h>

#define NN 100000
#define NE 1600000
#define SCAN_B 1024
#define SCAN_NB ((NN + SCAN_B - 1) / SCAN_B)   // 98

// Scratch (static device globals — no dynamic allocation allowed)
__device__ float4 g_zs[NN * 16];    // z * dinv   [N,64]
__device__ float4 g_agg1[NN * 16];  // layer-1 aggregation result [N,64]
__device__ float4 g_hs2[NN * 16];   // (x1@W2)*dinv [N,64]
__device__ float  g_dinv[NN];
__device__ int    g_cnt[NN];        // in-degree (edges only)
__device__ int    g_off[NN];        // CSR row offsets (exclusive prefix of cnt)
__device__ int    g_cur[NN];        // mutable cursor for permute
__device__ int    g_esrc[NE];       // src indices sorted by dst
__device__ int    g_bsum[128];      // scan block sums (raw totals from scan1)
__device__ int    g_layout;         // 1 = int64 pairs, 0 = int32

// Fused: zero g_cnt + detect edge_index storage (block 0 does detection).
__global__ void k_init(const int* __restrict__ ei) {
    int i = blockIdx.x * 256 + threadIdx.x;
    if (i < NN) g_cnt[i] = 0;
    if (blockIdx.x == 0) {
        __shared__ int nz;
        if (threadIdx.x == 0) nz = 0;
        __syncthreads();
        if (ei[2 * threadIdx.x + 1] != 0) atomicOr(&nz, 1);
        __syncthreads();
        if (threadIdx.x == 0) g_layout = (nz == 0) ? 1 : 0;
    }
}

__device__ __forceinline__ int edge_src(const int* __restrict__ ei, int e, int layout) {
    return layout ? ei[2 * e] : ei[e];
}
__device__ __forceinline__ int edge_dst(const int* __restrict__ ei, int e, int layout) {
    return layout ? ei[2 * (NE + e)] : ei[NE + e];
}

// Histogram of destinations, 4 edges/thread via int4 (int32 path)
__global__ void k_hist(const int* __restrict__ ei) {
    int t = blockIdx.x * 256 + threadIdx.x;
    int e = t * 4;
    if (e >= NE) return;
    if (g_layout == 0) {
        int4 d4 = __ldg((const int4*)(ei + NE) + t);
        if ((unsigned)d4.x < NN) atomicAdd(&g_cnt[d4.x], 1);
        if ((unsigned)d4.y < NN) atomicAdd(&g_cnt[d4.y], 1);
        if ((unsigned)d4.z < NN) atomicAdd(&g_cnt[d4.z], 1);
        if ((unsigned)d4.w < NN) atomicAdd(&g_cnt[d4.w], 1);
    } else {
#pragma unroll
        for (int q = 0; q < 4; ++q) {
            int d = edge_dst(ei, e + q, 1);
            if ((unsigned)d < NN) atomicAdd(&g_cnt[d], 1);
        }
    }
}

// Block-level exclusive scan (Hillis-Steele), emits per-block totals.
__global__ void k_scan1() {
    __shared__ int sh[SCAN_B];
    int i = blockIdx.x * SCAN_B + threadIdx.x;
    int v = (i < NN) ? g_cnt[i] : 0;
    sh[threadIdx.x] = v;
    __syncthreads();
#pragma unroll
    for (int ofs = 1; ofs < SCAN_B; ofs <<= 1) {
        int t = (threadIdx.x >= ofs) ? sh[threadIdx.x - ofs] : 0;
        __syncthreads();
        sh[threadIdx.x] += t;
        __syncthreads();
    }
    if (i < NN) g_off[i] = sh[threadIdx.x] - v;   // exclusive
    if (threadIdx.x == SCAN_B - 1) g_bsum[blockIdx.x] = sh[SCAN_B - 1];
}

// Fused scan2 + scan3 + scale_init: each block re-scans the 98 block sums
// in smem, then NN*16 threads finalize offsets / dinv / zs.
__global__ void k_prep(const float4* __restrict__ z4) {
    __shared__ int bs[128];
    int t = threadIdx.x;
    if (t < 128) bs[t] = (t < SCAN_NB) ? g_bsum[t] : 0;
    __syncthreads();
    int v0 = (t < 128) ? bs[t] : 0;
#pragma unroll
    for (int ofs = 1; ofs < 128; ofs <<= 1) {
        int tv = (t < 128 && t >= ofs) ? bs[t - ofs] : 0;
        __syncthreads();
        if (t < 128) bs[t] += tv;
        __syncthreads();
    }
    if (t < 128) bs[t] -= v0;   // exclusive
    __syncthreads();

    int u = blockIdx.x * 256 + t;  // exactly NN*16
    int node = u >> 4;
    int f = u & 15;
    float dinv = rsqrtf((float)g_cnt[node] + 1.0f);
    if (f == 0) {
        int o = g_off[node] + bs[node >> 10];
        g_off[node] = o;
        g_cur[node] = o;
        g_dinv[node] = dinv;
    }
    float4 v = __ldg(z4 + u);
    v.x *= dinv; v.y *= dinv; v.z *= dinv; v.w *= dinv;
    g_zs[u] = v;
}

// Counting-sort edges by destination, 4 edges/thread via int4 (int32 path)
__global__ void k_permute(const int* __restrict__ ei) {
    int t = blockIdx.x * 256 + threadIdx.x;
    int e = t * 4;
    if (e >= NE) return;
    if (g_layout == 0) {
        int4 s4 = __ldg((const int4*)ei + t);
        int4 d4 = __ldg((const int4*)(ei + NE) + t);
        if ((unsigned)s4.x < NN && (unsigned)d4.x < NN) g_esrc[atomicAdd(&g_cur[d4.x], 1)] = s4.x;
        if ((unsigned)s4.y < NN && (unsigned)d4.y < NN) g_esrc[atomicAdd(&g_cur[d4.y], 1)] = s4.y;
        if ((unsigned)s4.z < NN && (unsigned)d4.z < NN) g_esrc[atomicAdd(&g_cur[d4.z], 1)] = s4.z;
        if ((unsigned)s4.w < NN && (unsigned)d4.w < NN) g_esrc[atomicAdd(&g_cur[d4.w], 1)] = s4.w;
    } else {
#pragma unroll
        for (int q = 0; q < 4; ++q) {
            int s = edge_src(ei, e + q, 1);
            int d = edge_dst(ei, e + q, 1);
            if ((unsigned)s < NN && (unsigned)d < NN)
                g_esrc[atomicAdd(&g_cur[d], 1)] = s;
        }
    }
}

// Gather-side segment sum: 16 threads per node, one float4 column each.
template <bool FIRST>
__global__ void k_gather(float4* __restrict__ dout, const float4* __restrict__ b2v) {
    int gt = blockIdx.x * 256 + threadIdx.x;  // exactly NN*16 threads
    int node = gt >> 4;
    int f = gt & 15;
    const float4* hs = FIRST ? (const float4*)g_zs : (const float4*)g_hs2;
    float4 acc = __ldg(hs + (size_t)node * 16 + f);  // self-loop seed
    int j = g_off[node];
    int end = j + g_cnt[node];
    for (; j + 4 <= end; j += 4) {
        int s0 = __ldg(&g_esrc[j]);
        int s1 = __ldg(&g_esrc[j + 1]);
        int s2 = __ldg(&g_esrc[j + 2]);
        int s3 = __ldg(&g_esrc[j + 3]);
        float4 v0 = __ldg(hs + (size_t)s0 * 16 + f);
        float4 v1 = __ldg(hs + (size_t)s1 * 16 + f);
        float4 v2 = __ldg(hs + (size_t)s2 * 16 + f);
        float4 v3 = __ldg(hs + (size_t)s3 * 16 + f);
        acc.x += (v0.x + v1.x) + (v2.x + v3.x);
        acc.y += (v0.y + v1.y) + (v2.y + v3.y);
        acc.z += (v0.z + v1.z) + (v2.z + v3.z);
        acc.w += (v0.w + v1.w) + (v2.w + v3.w);
    }
    for (; j < end; ++j) {
        int s0 = __ldg(&g_esrc[j]);
        float4 v0 = __ldg(hs + (size_t)s0 * 16 + f);
        acc.x += v0.x; acc.y += v0.y; acc.z += v0.z; acc.w += v0.w;
    }
    if (FIRST) {
        g_agg1[(size_t)node * 16 + f] = acc;
    } else {
        float sc = g_dinv[node];
        float4 b = __ldg(b2v + f);
        acc.x = acc.x * sc + b.x; acc.y = acc.y * sc + b.y;
        acc.z = acc.z * sc + b.z; acc.w = acc.w * sc + b.w;
        dout[(size_t)node * 16 + f] = acc;
    }
}

// Fused two-layer GEMM: 64 rows/block, 256 threads.
// Phase 1: x1 = relu((agg1·dinv) @ W1 + b1)  -> smem
// Phase 2: hs2 = (x1 @ W2) * dinv            -> global
// smem: W1s 32KB | W2s 32KB | Xs 33.8KB (input rows phase1, x1 tile phase2)
__global__ void __launch_bounds__(256) k_gemm_fused(const float* __restrict__ W1,
                                                    const float* __restrict__ b1,
                                                    const float* __restrict__ W2) {
    extern __shared__ __align__(16) float smem[];
    float* W1s = smem;                 // 64*128 = 8192 floats
    float* W2s = smem + 8192;          // 128*64 = 8192 floats
    float* Xs  = smem + 16384;         // 64*132 = 8448 floats

    int tid = threadIdx.x;
    int row0 = blockIdx.x * 64;

    // Stage W1, W2 (float4)
    {
        float4* d1 = (float4*)W1s; const float4* s1 = (const float4*)W1;
        float4* d2 = (float4*)W2s; const float4* s2 = (const float4*)W2;
#pragma unroll
        for (int j = tid; j < 2048; j += 256) { d1[j] = __ldg(s1 + j); d2[j] = __ldg(s2 + j); }
    }
    // Stage input rows (agg1, scaled by dinv) into Xs with stride 68
#pragma unroll
    for (int j = tid; j < 64 * 16; j += 256) {
        int r = j >> 4, c4 = j & 15;
        int grow = row0 + r; if (grow >= NN) grow = NN - 1;
        float4 v = __ldg((const float4*)g_agg1 + (size_t)grow * 16 + c4);
        float sc = g_dinv[grow];
        v.x *= sc; v.y *= sc; v.z *= sc; v.w *= sc;
        *(float4*)&Xs[r * 68 + c4 * 4] = v;
    }
    __syncthreads();

    // ---- Phase 1: 64x128 = (64x64)@(64x128). TPR=16, R=4. ----
    int c = tid & 15;        // 0..15, 8 output cols each
    int g = tid >> 4;        // 0..15 row groups
    float4 a0[4], a1[4];
#pragma unroll
    for (int i = 0; i < 4; ++i) {
        a0[i] = make_float4(0.f, 0.f, 0.f, 0.f);
        a1[i] = make_float4(0.f, 0.f, 0.f, 0.f);
    }
    {
        const float4* Wr = (const float4*)W1s;
#pragma unroll
        for (int kk4 = 0; kk4 < 16; ++kk4) {
            float4 zk[4];
#pragma unroll
            for (int i = 0; i < 4; ++i)
                zk[i] = *(const float4*)&Xs[(g * 4 + i) * 68 + kk4 * 4];
#pragma unroll
            for (int kc = 0; kc < 4; ++kc) {
                float4 w0 = Wr[(kk4 * 4 + kc) * 32 + 2 * c];
                float4 w1 = Wr[(kk4 * 4 + kc) * 32 + 2 * c + 1];
#pragma unroll
                for (int i = 0; i < 4; ++i) {
                    float z = (kc == 0) ? zk[i].x : (kc == 1) ? zk[i].y
                             : (kc == 2) ? zk[i].z : zk[i].w;
                    a0[i].x += z * w0.x; a0[i].y += z * w0.y;
                    a0[i].z += z * w0.z; a0[i].w += z * w0.w;
                    a1[i].x += z * w1.x; a1[i].y += z * w1.y;
                    a1[i].z += z * w1.z; a1[i].w += z * w1.w;
                }
            }
        }
    }
    __syncthreads();   // input staging reads done; reuse Xs for x1 (stride 132)

    {
        float4 bb0 = __ldg((const float4*)b1 + 2 * c);
        float4 bb1 = __ldg((const float4*)b1 + 2 * c + 1);
#pragma unroll
        for (int i = 0; i < 4; ++i) {
            int r = g * 4 + i;
            float4 v0, v1;
            v0.x = fmaxf(a0[i].x + bb0.x, 0.f); v0.y = fmaxf(a0[i].y + bb0.y, 0.f);
            v0.z = fmaxf(a0[i].z + bb0.z, 0.f); v0.w = fmaxf(a0[i].w + bb0.w, 0.f);
            v1.x = fmaxf(a1[i].x + bb1.x, 0.f); v1.y = fmaxf(a1[i].y + bb1.y, 0.f);
            v1.z = fmaxf(a1[i].z + bb1.z, 0.f); v1.w = fmaxf(a1[i].w + bb1.w, 0.f);
            *(float4*)&Xs[r * 132 + c * 8]     = v0;
            *(float4*)&Xs[r * 132 + c * 8 + 4] = v1;
        }
    }
    __syncthreads();

    // ---- Phase 2: 64x64 = (64x128)@(128x64). TPR=8, R=2. ----
    int c2 = tid & 7;        // 8 output cols each
    int g2 = tid >> 3;       // 0..31 row groups
    float4 d0[2], d1[2];
#pragma unroll
    for (int i = 0; i < 2; ++i) {
        d0[i] = make_float4(0.f, 0.f, 0.f, 0.f);
        d1[i] = make_float4(0.f, 0.f, 0.f, 0.f);
    }
    {
        const float4* Wr = (const float4*)W2s;
#pragma unroll
        for (int kk4 = 0; kk4 < 32; ++kk4) {
            float4 zk[2];
#pragma unroll
            for (int i = 0; i < 2; ++i)
                zk[i] = *(const float4*)&Xs[(g2 * 2 + i) * 132 + kk4 * 4];
#pragma unroll
            for (int kc = 0; kc < 4; ++kc) {
                float4 w0 = Wr[(kk4 * 4 + kc) * 16 + 2 * c2];
                float4 w1 = Wr[(kk4 * 4 + kc) * 16 + 2 * c2 + 1];
#pragma unroll
                for (int i = 0; i < 2; ++i) {
                    float z = (kc == 0) ? zk[i].x : (kc == 1) ? zk[i].y
                             : (kc == 2) ? zk[i].z : zk[i].w;
                    d0[i].x += z * w0.x; d0[i].y += z * w0.y;
                    d0[i].z += z * w0.z; d0[i].w += z * w0.w;
                    d1[i].x += z * w1.x; d1[i].y += z * w1.y;
                    d1[i].z += z * w1.z; d1[i].w += z * w1.w;
                }
            }
        }
    }
#pragma unroll
    for (int i = 0; i < 2; ++i) {
        int grow = row0 + g2 * 2 + i;
        if (grow >= NN) continue;
        float sc = g_dinv[grow];
        float4 v0, v1;
        v0.x = d0[i].x * sc; v0.y = d0[i].y * sc; v0.z = d0[i].z * sc; v0.w = d0[i].w * sc;
        v1.x = d1[i].x * sc; v1.y = d1[i].y * sc; v1.z = d1[i].z * sc; v1.w = d1[i].w * sc;
        float4* h = (float4*)g_hs2 + (size_t)grow * 16;
        h[2 * c2] = v0;
        h[2 * c2 + 1] = v1;
    }
}

extern "C" void kernel_launch(void* const* d_in, const int* in_sizes, int n_in,
                              void* d_out, int out_size) {
    const float* z   = (const float*)d_in[0];
    const int* ei    = (const int*)d_in[1];   // int32 OR int64 pairs (detected)
    const float* W1  = (const float*)d_in[2];
    const float* b1  = (const float*)d_in[3];
    const float* W2  = (const float*)d_in[4];
    const float* b2  = (const float*)d_in[5];
    float* out = (float*)d_out;

    const int fused_smem = (8192 + 8192 + 64 * 132) * 4;  // 99328 bytes
    cudaFuncSetAttribute(k_gemm_fused, cudaFuncAttributeMaxDynamicSharedMemorySize, fused_smem);

    k_init<<<(NN + 255) / 256, 256>>>(ei);
    k_hist<<<(NE / 4 + 255) / 256, 256>>>(ei);
    k_scan1<<<SCAN_NB, SCAN_B>>>();
    k_prep<<<NN * 16 / 256, 256>>>((const float4*)z);
    k_permute<<<(NE / 4 + 255) / 256, 256>>>(ei);
    k_gather<true><<<NN * 16 / 256, 256>>>(nullptr, nullptr);
    k_gemm_fused<<<(NN + 63) / 64, 256, fused_smem>>>(W1, b1, W2);
    k_gather<false><<<NN * 16 / 256, 256>>>((float4*)out, (const float4*)b2);
}

// round 12
// speedup vs baseline: 1.1193x; 1.1193x over previous
#include <cuda_runtime.h>

#define NN 100000
#define NE 1600000
#define SCAN_B 1024
#define SCAN_NB ((NN + SCAN_B - 1) / SCAN_B)   // 98

// Scratch (static device globals — no dynamic allocation allowed)
__device__ float4 g_zs[NN * 16];    // z * dinv   [N,64]
__device__ float4 g_agg1[NN * 16];  // layer-1 aggregation result [N,64]
__device__ float4 g_x1[NN * 32];    // relu(gcn1) [N,128]
__device__ float4 g_hs2[NN * 16];   // (x1@W2)*dinv [N,64]
__device__ float  g_dinv[NN];
__device__ int    g_cnt[NN];        // in-degree (edges only)
__device__ int    g_off[NN];        // CSR row offsets (exclusive prefix of cnt)
__device__ int    g_cur[NN];        // mutable cursor for permute
__device__ int    g_esrc[NE];       // src indices sorted by dst
__device__ int    g_bsum[128];      // scan block sums (raw totals from scan1)
__device__ int    g_layout;         // 1 = int64 pairs, 0 = int32

// Fused: zero g_cnt + detect edge_index storage (block 0 does detection).
__global__ void k_init(const int* __restrict__ ei) {
    int i = blockIdx.x * 256 + threadIdx.x;
    if (i < NN) g_cnt[i] = 0;
    if (blockIdx.x == 0) {
        __shared__ int nz;
        if (threadIdx.x == 0) nz = 0;
        __syncthreads();
        if (ei[2 * threadIdx.x + 1] != 0) atomicOr(&nz, 1);
        __syncthreads();
        if (threadIdx.x == 0) g_layout = (nz == 0) ? 1 : 0;
    }
}

__device__ __forceinline__ int edge_src(const int* __restrict__ ei, int e, int layout) {
    return layout ? ei[2 * e] : ei[e];
}
__device__ __forceinline__ int edge_dst(const int* __restrict__ ei, int e, int layout) {
    return layout ? ei[2 * (NE + e)] : ei[NE + e];
}

// Histogram of destinations, 4 edges/thread via int4 (int32 path)
__global__ void k_hist(const int* __restrict__ ei) {
    int t = blockIdx.x * 256 + threadIdx.x;
    int e = t * 4;
    if (e >= NE) return;
    if (g_layout == 0) {
        int4 d4 = __ldg((const int4*)(ei + NE) + t);
        if ((unsigned)d4.x < NN) atomicAdd(&g_cnt[d4.x], 1);
        if ((unsigned)d4.y < NN) atomicAdd(&g_cnt[d4.y], 1);
        if ((unsigned)d4.z < NN) atomicAdd(&g_cnt[d4.z], 1);
        if ((unsigned)d4.w < NN) atomicAdd(&g_cnt[d4.w], 1);
    } else {
#pragma unroll
        for (int q = 0; q < 4; ++q) {
            int d = edge_dst(ei, e + q, 1);
            if ((unsigned)d < NN) atomicAdd(&g_cnt[d], 1);
        }
    }
}

// Block-level exclusive scan (Hillis-Steele), emits per-block totals.
__global__ void k_scan1() {
    __shared__ int sh[SCAN_B];
    int i = blockIdx.x * SCAN_B + threadIdx.x;
    int v = (i < NN) ? g_cnt[i] : 0;
    sh[threadIdx.x] = v;
    __syncthreads();
#pragma unroll
    for (int ofs = 1; ofs < SCAN_B; ofs <<= 1) {
        int t = (threadIdx.x >= ofs) ? sh[threadIdx.x - ofs] : 0;
        __syncthreads();
        sh[threadIdx.x] += t;
        __syncthreads();
    }
    if (i < NN) g_off[i] = sh[threadIdx.x] - v;   // exclusive
    if (threadIdx.x == SCAN_B - 1) g_bsum[blockIdx.x] = sh[SCAN_B - 1];
}

// Fused scan2 + scan3 + scale_init: each block re-scans the 98 block sums
// in smem, then NN*16 threads finalize offsets / dinv / zs.
__global__ void k_prep(const float4* __restrict__ z4) {
    __shared__ int bs[128];
    int t = threadIdx.x;
    if (t < 128) bs[t] = (t < SCAN_NB) ? g_bsum[t] : 0;
    __syncthreads();
    int v0 = (t < 128) ? bs[t] : 0;
#pragma unroll
    for (int ofs = 1; ofs < 128; ofs <<= 1) {
        int tv = (t < 128 && t >= ofs) ? bs[t - ofs] : 0;
        __syncthreads();
        if (t < 128) bs[t] += tv;
        __syncthreads();
    }
    if (t < 128) bs[t] -= v0;   // exclusive
    __syncthreads();

    int u = blockIdx.x * 256 + t;  // exactly NN*16
    int node = u >> 4;
    int f = u & 15;
    float dinv = rsqrtf((float)g_cnt[node] + 1.0f);
    if (f == 0) {
        int o = g_off[node] + bs[node >> 10];
        g_off[node] = o;
        g_cur[node] = o;
        g_dinv[node] = dinv;
    }
    float4 v = __ldg(z4 + u);
    v.x *= dinv; v.y *= dinv; v.z *= dinv; v.w *= dinv;
    g_zs[u] = v;
}

// Counting-sort edges by destination, 4 edges/thread via int4 (int32 path)
__global__ void k_permute(const int* __restrict__ ei) {
    int t = blockIdx.x * 256 + threadIdx.x;
    int e = t * 4;
    if (e >= NE) return;
    if (g_layout == 0) {
        int4 s4 = __ldg((const int4*)ei + t);
        int4 d4 = __ldg((const int4*)(ei + NE) + t);
        if ((unsigned)s4.x < NN && (unsigned)d4.x < NN) g_esrc[atomicAdd(&g_cur[d4.x], 1)] = s4.x;
        if ((unsigned)s4.y < NN && (unsigned)d4.y < NN) g_esrc[atomicAdd(&g_cur[d4.y], 1)] = s4.y;
        if ((unsigned)s4.z < NN && (unsigned)d4.z < NN) g_esrc[atomicAdd(&g_cur[d4.z], 1)] = s4.z;
        if ((unsigned)s4.w < NN && (unsigned)d4.w < NN) g_esrc[atomicAdd(&g_cur[d4.w], 1)] = s4.w;
    } else {
#pragma unroll
        for (int q = 0; q < 4; ++q) {
            int s = edge_src(ei, e + q, 1);
            int d = edge_dst(ei, e + q, 1);
            if ((unsigned)s < NN && (unsigned)d < NN)
                g_esrc[atomicAdd(&g_cur[d], 1)] = s;
        }
    }
}

// Gather-side segment sum: 16 threads per node, one float4 column each.
template <bool FIRST>
__global__ void k_gather(float4* __restrict__ dout, const float4* __restrict__ b2v) {
    int gt = blockIdx.x * 256 + threadIdx.x;  // exactly NN*16 threads
    int node = gt >> 4;
    int f = gt & 15;
    const float4* hs = FIRST ? (const float4*)g_zs : (const float4*)g_hs2;
    float4 acc = __ldg(hs + (size_t)node * 16 + f);  // self-loop seed
    int j = g_off[node];
    int end = j + g_cnt[node];
    for (; j + 4 <= end; j += 4) {
        int s0 = __ldg(&g_esrc[j]);
        int s1 = __ldg(&g_esrc[j + 1]);
        int s2 = __ldg(&g_esrc[j + 2]);
        int s3 = __ldg(&g_esrc[j + 3]);
        float4 v0 = __ldg(hs + (size_t)s0 * 16 + f);
        float4 v1 = __ldg(hs + (size_t)s1 * 16 + f);
        float4 v2 = __ldg(hs + (size_t)s2 * 16 + f);
        float4 v3 = __ldg(hs + (size_t)s3 * 16 + f);
        acc.x += (v0.x + v1.x) + (v2.x + v3.x);
        acc.y += (v0.y + v1.y) + (v2.y + v3.y);
        acc.z += (v0.z + v1.z) + (v2.z + v3.z);
        acc.w += (v0.w + v1.w) + (v2.w + v3.w);
    }
    for (; j < end; ++j) {
        int s0 = __ldg(&g_esrc[j]);
        float4 v0 = __ldg(hs + (size_t)s0 * 16 + f);
        acc.x += v0.x; acc.y += v0.y; acc.z += v0.z; acc.w += v0.w;
    }
    if (FIRST) {
        g_agg1[(size_t)node * 16 + f] = acc;
    } else {
        float sc = g_dinv[node];
        float4 b = __ldg(b2v + f);
        acc.x = acc.x * sc + b.x; acc.y = acc.y * sc + b.y;
        acc.z = acc.z * sc + b.z; acc.w = acc.w * sc + b.w;
        dout[(size_t)node * 16 + f] = acc;
    }
}

// Dense GEMM: ROWS rows/block, 256 threads, R=4 rows/thread, float4 zk loads.
// (Separate per layer — high occupancy beats the fused low-occupancy variant.)
// EPI==1: in = g_agg1 (rows scaled by dinv at load), out = relu(acc + b1) -> g_x1
// EPI==2: in = g_x1,  out = acc * dinv[row] -> g_hs2   (pre-scale by dinv[src])
template <int K, int N, int ROWS, int EPI>
__global__ void __launch_bounds__(256) k_gemm(const float* __restrict__ W,
                                              const float* __restrict__ bias) {
    constexpr int TPR = N / 8;          // threads per row-group (8 outputs each)
    constexpr int GROUPS = 256 / TPR;   // row groups per block
    constexpr int R = ROWS / GROUPS;    // rows per thread (4)
    constexpr int KT = 32;
    constexpr int RST = KT + 4;         // float stride, keeps float4 alignment

    __shared__ __align__(16) float Ws[KT * N];
    __shared__ __align__(16) float Rs[ROWS * RST];

    const float* in = (EPI == 1) ? (const float*)g_agg1 : (const float*)g_x1;

    int tid = threadIdx.x;
    int c = tid % TPR;
    int g = tid / TPR;
    int row0 = blockIdx.x * ROWS;

    float4 a0[R], a1[R];
#pragma unroll
    for (int i = 0; i < R; i++) {
        a0[i] = make_float4(0.f, 0.f, 0.f, 0.f);
        a1[i] = make_float4(0.f, 0.f, 0.f, 0.f);
    }

#pragma unroll
    for (int kt = 0; kt < K / KT; ++kt) {
        const float4* Wg = (const float4*)(W + kt * KT * N);
        float4* Ws4 = (float4*)Ws;
#pragma unroll
        for (int j = tid; j < KT * N / 4; j += 256) Ws4[j] = __ldg(Wg + j);
#pragma unroll
        for (int j = tid; j < ROWS * (KT / 4); j += 256) {
            int r = j / (KT / 4), c4 = j % (KT / 4);
            int grow = row0 + r;
            if (grow >= NN) grow = NN - 1;
            float4 v = __ldg((const float4*)(in + (size_t)grow * K + kt * KT) + c4);
            if (EPI == 1) {
                float sc = g_dinv[grow];
                v.x *= sc; v.y *= sc; v.z *= sc; v.w *= sc;
            }
            *(float4*)&Rs[r * RST + c4 * 4] = v;
        }
        __syncthreads();

        const float4* Wr = (const float4*)Ws;
#pragma unroll
        for (int kk4 = 0; kk4 < KT / 4; ++kk4) {
            float4 zk[R];
#pragma unroll
            for (int i = 0; i < R; ++i)
                zk[i] = *(const float4*)&Rs[(g * R + i) * RST + kk4 * 4];
#pragma unroll
            for (int kc = 0; kc < 4; ++kc) {
                float4 w0 = Wr[(kk4 * 4 + kc) * (N / 4) + 2 * c];
                float4 w1 = Wr[(kk4 * 4 + kc) * (N / 4) + 2 * c + 1];
#pragma unroll
                for (int i = 0; i < R; ++i) {
                    float z = (kc == 0) ? zk[i].x : (kc == 1) ? zk[i].y
                             : (kc == 2) ? zk[i].z : zk[i].w;
                    a0[i].x += z * w0.x; a0[i].y += z * w0.y;
                    a0[i].z += z * w0.z; a0[i].w += z * w0.w;
                    a1[i].x += z * w1.x; a1[i].y += z * w1.y;
                    a1[i].z += z * w1.z; a1[i].w += z * w1.w;
                }
            }
        }
        __syncthreads();
    }

#pragma unroll
    for (int i = 0; i < R; ++i) {
        int grow = row0 + g * R + i;
        if (grow >= NN) continue;
        if (EPI == 1) {
            float4 bb0 = __ldg((const float4*)bias + 2 * c);
            float4 bb1 = __ldg((const float4*)bias + 2 * c + 1);
            float4 v0, v1;
            v0.x = fmaxf(a0[i].x + bb0.x, 0.f); v0.y = fmaxf(a0[i].y + bb0.y, 0.f);
            v0.z = fmaxf(a0[i].z + bb0.z, 0.f); v0.w = fmaxf(a0[i].w + bb0.w, 0.f);
            v1.x = fmaxf(a1[i].x + bb1.x, 0.f); v1.y = fmaxf(a1[i].y + bb1.y, 0.f);
            v1.z = fmaxf(a1[i].z + bb1.z, 0.f); v1.w = fmaxf(a1[i].w + bb1.w, 0.f);
            float4* op = (float4*)g_x1 + (size_t)grow * (N / 4);
            op[2 * c] = v0;
            op[2 * c + 1] = v1;
        } else {
            float sc = g_dinv[grow];
            float4 v0, v1;
            v0.x = a0[i].x * sc; v0.y = a0[i].y * sc; v0.z = a0[i].z * sc; v0.w = a0[i].w * sc;
            v1.x = a1[i].x * sc; v1.y = a1[i].y * sc; v1.z = a1[i].z * sc; v1.w = a1[i].w * sc;
            float4* h = (float4*)g_hs2 + (size_t)grow * (N / 4);
            h[2 * c] = v0;
            h[2 * c + 1] = v1;
        }
    }
}

extern "C" void kernel_launch(void* const* d_in, const int* in_sizes, int n_in,
                              void* d_out, int out_size) {
    const float* z   = (const float*)d_in[0];
    const int* ei    = (const int*)d_in[1];   // int32 OR int64 pairs (detected)
    const float* W1  = (const float*)d_in[2];
    const float* b1  = (const float*)d_in[3];
    const float* W2  = (const float*)d_in[4];
    const float* b2  = (const float*)d_in[5];
    float* out = (float*)d_out;

    k_init<<<(NN + 255) / 256, 256>>>(ei);
    k_hist<<<(NE / 4 + 255) / 256, 256>>>(ei);
    k_scan1<<<SCAN_NB, SCAN_B>>>();
    k_prep<<<NN * 16 / 256, 256>>>((const float4*)z);
    k_permute<<<(NE / 4 + 255) / 256, 256>>>(ei);
    k_gather<true><<<NN * 16 / 256, 256>>>(nullptr, nullptr);
    k_gemm<64, 128, 64, 1><<<(NN + 63) / 64, 256>>>(W1, b1);
    k_gemm<128, 64, 128, 2><<<(NN + 127) / 128, 256>>>(W2, nullptr);
    k_gather<false><<<NN * 16 / 256, 256>>>((float4*)out, (const float4*)b2);
}

// round 13
// speedup vs baseline: 1.1976x; 1.0699x over previous
#include <cuda_runtime.h>
#include <cuda_fp16.h>

#define NN 100000
#define NE 1600000
#define SCAN_B 1024
#define SCAN_NB ((NN + SCAN_B - 1) / SCAN_B)   // 98

// Scratch (static device globals — no dynamic allocation allowed)
__device__ uint2  g_zsh[NN * 16];   // z * dinv   [N,64] as fp16 (4 halfs per uint2)
__device__ float4 g_agg1[NN * 16];  // layer-1 aggregation result [N,64] fp32
__device__ float4 g_x1[NN * 32];    // relu(gcn1) [N,128] fp32
__device__ uint2  g_hs2h[NN * 16];  // (x1@W2)*dinv [N,64] as fp16
__device__ float  g_dinv[NN];
__device__ int    g_cnt[NN];        // in-degree (edges only)
__device__ int    g_off[NN];        // CSR row offsets (exclusive prefix of cnt)
__device__ int    g_cur[NN];        // mutable cursor for permute
__device__ int    g_esrc[NE];       // src indices sorted by dst
__device__ int    g_bsum[128];      // scan block sums (raw totals from scan1)
__device__ int    g_layout;         // 1 = int64 pairs, 0 = int32

__device__ __forceinline__ uint2 pack_h4(float4 v) {
    __half2 a = __floats2half2_rn(v.x, v.y);
    __half2 b = __floats2half2_rn(v.z, v.w);
    uint2 u;
    u.x = *(unsigned*)&a;
    u.y = *(unsigned*)&b;
    return u;
}
__device__ __forceinline__ void acc_h4(float4& acc, uint2 u) {
    float2 f0 = __half22float2(*(__half2*)&u.x);
    float2 f1 = __half22float2(*(__half2*)&u.y);
    acc.x += f0.x; acc.y += f0.y; acc.z += f1.x; acc.w += f1.y;
}

// Fused: zero g_cnt + detect edge_index storage (block 0 does detection).
__global__ void k_init(const int* __restrict__ ei) {
    int i = blockIdx.x * 256 + threadIdx.x;
    if (i < NN) g_cnt[i] = 0;
    if (blockIdx.x == 0) {
        __shared__ int nz;
        if (threadIdx.x == 0) nz = 0;
        __syncthreads();
        if (ei[2 * threadIdx.x + 1] != 0) atomicOr(&nz, 1);
        __syncthreads();
        if (threadIdx.x == 0) g_layout = (nz == 0) ? 1 : 0;
    }
}

__device__ __forceinline__ int edge_src(const int* __restrict__ ei, int e, int layout) {
    return layout ? ei[2 * e] : ei[e];
}
__device__ __forceinline__ int edge_dst(const int* __restrict__ ei, int e, int layout) {
    return layout ? ei[2 * (NE + e)] : ei[NE + e];
}

// Histogram of destinations, 4 edges/thread via int4 (int32 path)
__global__ void k_hist(const int* __restrict__ ei) {
    int t = blockIdx.x * 256 + threadIdx.x;
    int e = t * 4;
    if (e >= NE) return;
    if (g_layout == 0) {
        int4 d4 = __ldg((const int4*)(ei + NE) + t);
        if ((unsigned)d4.x < NN) atomicAdd(&g_cnt[d4.x], 1);
        if ((unsigned)d4.y < NN) atomicAdd(&g_cnt[d4.y], 1);
        if ((unsigned)d4.z < NN) atomicAdd(&g_cnt[d4.z], 1);
        if ((unsigned)d4.w < NN) atomicAdd(&g_cnt[d4.w], 1);
    } else {
#pragma unroll
        for (int q = 0; q < 4; ++q) {
            int d = edge_dst(ei, e + q, 1);
            if ((unsigned)d < NN) atomicAdd(&g_cnt[d], 1);
        }
    }
}

// Block-level exclusive scan (Hillis-Steele), emits per-block totals.
__global__ void k_scan1() {
    __shared__ int sh[SCAN_B];
    int i = blockIdx.x * SCAN_B + threadIdx.x;
    int v = (i < NN) ? g_cnt[i] : 0;
    sh[threadIdx.x] = v;
    __syncthreads();
#pragma unroll
    for (int ofs = 1; ofs < SCAN_B; ofs <<= 1) {
        int t = (threadIdx.x >= ofs) ? sh[threadIdx.x - ofs] : 0;
        __syncthreads();
        sh[threadIdx.x] += t;
        __syncthreads();
    }
    if (i < NN) g_off[i] = sh[threadIdx.x] - v;   // exclusive
    if (threadIdx.x == SCAN_B - 1) g_bsum[blockIdx.x] = sh[SCAN_B - 1];
}

// Fused scan2 + scan3 + scale_init: each block re-scans the 98 block sums
// in smem, then NN*16 threads finalize offsets / dinv / zs (fp16).
__global__ void k_prep(const float4* __restrict__ z4) {
    __shared__ int bs[128];
    int t = threadIdx.x;
    if (t < 128) bs[t] = (t < SCAN_NB) ? g_bsum[t] : 0;
    __syncthreads();
    int v0 = (t < 128) ? bs[t] : 0;
#pragma unroll
    for (int ofs = 1; ofs < 128; ofs <<= 1) {
        int tv = (t < 128 && t >= ofs) ? bs[t - ofs] : 0;
        __syncthreads();
        if (t < 128) bs[t] += tv;
        __syncthreads();
    }
    if (t < 128) bs[t] -= v0;   // exclusive
    __syncthreads();

    int u = blockIdx.x * 256 + t;  // exactly NN*16
    int node = u >> 4;
    int f = u & 15;
    float dinv = rsqrtf((float)g_cnt[node] + 1.0f);
    if (f == 0) {
        int o = g_off[node] + bs[node >> 10];
        g_off[node] = o;
        g_cur[node] = o;
        g_dinv[node] = dinv;
    }
    float4 v = __ldg(z4 + u);
    v.x *= dinv; v.y *= dinv; v.z *= dinv; v.w *= dinv;
    g_zsh[u] = pack_h4(v);
}

// Counting-sort edges by destination, 4 edges/thread via int4 (int32 path)
__global__ void k_permute(const int* __restrict__ ei) {
    int t = blockIdx.x * 256 + threadIdx.x;
    int e = t * 4;
    if (e >= NE) return;
    if (g_layout == 0) {
        int4 s4 = __ldg((const int4*)ei + t);
        int4 d4 = __ldg((const int4*)(ei + NE) + t);
        if ((unsigned)s4.x < NN && (unsigned)d4.x < NN) g_esrc[atomicAdd(&g_cur[d4.x], 1)] = s4.x;
        if ((unsigned)s4.y < NN && (unsigned)d4.y < NN) g_esrc[atomicAdd(&g_cur[d4.y], 1)] = s4.y;
        if ((unsigned)s4.z < NN && (unsigned)d4.z < NN) g_esrc[atomicAdd(&g_cur[d4.z], 1)] = s4.z;
        if ((unsigned)s4.w < NN && (unsigned)d4.w < NN) g_esrc[atomicAdd(&g_cur[d4.w], 1)] = s4.w;
    } else {
#pragma unroll
        for (int q = 0; q < 4; ++q) {
            int s = edge_src(ei, e + q, 1);
            int d = edge_dst(ei, e + q, 1);
            if ((unsigned)s < NN && (unsigned)d < NN)
                g_esrc[atomicAdd(&g_cur[d], 1)] = s;
        }
    }
}

// Gather-side segment sum: 16 threads per node, one 4-feature column each.
// Payload rows are fp16 (uint2 = 4 halfs); accumulation in fp32.
template <bool FIRST>
__global__ void k_gather(float4* __restrict__ dout, const float4* __restrict__ b2v) {
    int gt = blockIdx.x * 256 + threadIdx.x;  // exactly NN*16 threads
    int node = gt >> 4;
    int f = gt & 15;
    const uint2* hs = FIRST ? (const uint2*)g_zsh : (const uint2*)g_hs2h;
    float4 acc = make_float4(0.f, 0.f, 0.f, 0.f);
    acc_h4(acc, __ldg(hs + (size_t)node * 16 + f));  // self-loop seed
    int j = g_off[node];
    int end = j + g_cnt[node];
    for (; j + 4 <= end; j += 4) {
        int s0 = __ldg(&g_esrc[j]);
        int s1 = __ldg(&g_esrc[j + 1]);
        int s2 = __ldg(&g_esrc[j + 2]);
        int s3 = __ldg(&g_esrc[j + 3]);
        uint2 u0 = __ldg(hs + (size_t)s0 * 16 + f);
        uint2 u1 = __ldg(hs + (size_t)s1 * 16 + f);
        uint2 u2 = __ldg(hs + (size_t)s2 * 16 + f);
        uint2 u3 = __ldg(hs + (size_t)s3 * 16 + f);
        acc_h4(acc, u0); acc_h4(acc, u1); acc_h4(acc, u2); acc_h4(acc, u3);
    }
    for (; j < end; ++j) {
        int s0 = __ldg(&g_esrc[j]);
        acc_h4(acc, __ldg(hs + (size_t)s0 * 16 + f));
    }
    if (FIRST) {
        g_agg1[(size_t)node * 16 + f] = acc;
    } else {
        float sc = g_dinv[node];
        float4 b = __ldg(b2v + f);
        acc.x = acc.x * sc + b.x; acc.y = acc.y * sc + b.y;
        acc.z = acc.z * sc + b.z; acc.w = acc.w * sc + b.w;
        dout[(size_t)node * 16 + f] = acc;
    }
}

// Dense GEMM: ROWS rows/block, 256 threads, R=4 rows/thread, float4 zk loads.
// EPI==1: in = g_agg1 (rows scaled by dinv at load), out = relu(acc + b1) -> g_x1
// EPI==2: in = g_x1,  out = (acc * dinv[row]) as fp16 -> g_hs2h
template <int K, int N, int ROWS, int EPI>
__global__ void __launch_bounds__(256) k_gemm(const float* __restrict__ W,
                                              const float* __restrict__ bias) {
    constexpr int TPR = N / 8;          // threads per row-group (8 outputs each)
    constexpr int GROUPS = 256 / TPR;   // row groups per block
    constexpr int R = ROWS / GROUPS;    // rows per thread (4)
    constexpr int KT = 32;
    constexpr int RST = KT + 4;         // float stride, keeps float4 alignment

    __shared__ __align__(16) float Ws[KT * N];
    __shared__ __align__(16) float Rs[ROWS * RST];

    const float* in = (EPI == 1) ? (const float*)g_agg1 : (const float*)g_x1;

    int tid = threadIdx.x;
    int c = tid % TPR;
    int g = tid / TPR;
    int row0 = blockIdx.x * ROWS;

    float4 a0[R], a1[R];
#pragma unroll
    for (int i = 0; i < R; i++) {
        a0[i] = make_float4(0.f, 0.f, 0.f, 0.f);
        a1[i] = make_float4(0.f, 0.f, 0.f, 0.f);
    }

#pragma unroll
    for (int kt = 0; kt < K / KT; ++kt) {
        const float4* Wg = (const float4*)(W + kt * KT * N);
        float4* Ws4 = (float4*)Ws;
#pragma unroll
        for (int j = tid; j < KT * N / 4; j += 256) Ws4[j] = __ldg(Wg + j);
#pragma unroll
        for (int j = tid; j < ROWS * (KT / 4); j += 256) {
            int r = j / (KT / 4), c4 = j % (KT / 4);
            int grow = row0 + r;
            if (grow >= NN) grow = NN - 1;
            float4 v = __ldg((const float4*)(in + (size_t)grow * K + kt * KT) + c4);
            if (EPI == 1) {
                float sc = g_dinv[grow];
                v.x *= sc; v.y *= sc; v.z *= sc; v.w *= sc;
            }
            *(float4*)&Rs[r * RST + c4 * 4] = v;
        }
        __syncthreads();

        const float4* Wr = (const float4*)Ws;
#pragma unroll
        for (int kk4 = 0; kk4 < KT / 4; ++kk4) {
            float4 zk[R];
#pragma unroll
            for (int i = 0; i < R; ++i)
                zk[i] = *(const float4*)&Rs[(g * R + i) * RST + kk4 * 4];
#pragma unroll
            for (int kc = 0; kc < 4; ++kc) {
                float4 w0 = Wr[(kk4 * 4 + kc) * (N / 4) + 2 * c];
                float4 w1 = Wr[(kk4 * 4 + kc) * (N / 4) + 2 * c + 1];
#pragma unroll
                for (int i = 0; i < R; ++i) {
                    float z = (kc == 0) ? zk[i].x : (kc == 1) ? zk[i].y
                             : (kc == 2) ? zk[i].z : zk[i].w;
                    a0[i].x += z * w0.x; a0[i].y += z * w0.y;
                    a0[i].z += z * w0.z; a0[i].w += z * w0.w;
                    a1[i].x += z * w1.x; a1[i].y += z * w1.y;
                    a1[i].z += z * w1.z; a1[i].w += z * w1.w;
                }
            }
        }
        __syncthreads();
    }

#pragma unroll
    for (int i = 0; i < R; ++i) {
        int grow = row0 + g * R + i;
        if (grow >= NN) continue;
        if (EPI == 1) {
            float4 bb0 = __ldg((const float4*)bias + 2 * c);
            float4 bb1 = __ldg((const float4*)bias + 2 * c + 1);
            float4 v0, v1;
            v0.x = fmaxf(a0[i].x + bb0.x, 0.f); v0.y = fmaxf(a0[i].y + bb0.y, 0.f);
            v0.z = fmaxf(a0[i].z + bb0.z, 0.f); v0.w = fmaxf(a0[i].w + bb0.w, 0.f);
            v1.x = fmaxf(a1[i].x + bb1.x, 0.f); v1.y = fmaxf(a1[i].y + bb1.y, 0.f);
            v1.z = fmaxf(a1[i].z + bb1.z, 0.f); v1.w = fmaxf(a1[i].w + bb1.w, 0.f);
            float4* op = (float4*)g_x1 + (size_t)grow * (N / 4);
            op[2 * c] = v0;
            op[2 * c + 1] = v1;
        } else {
            float sc = g_dinv[grow];
            float4 v0, v1;
            v0.x = a0[i].x * sc; v0.y = a0[i].y * sc; v0.z = a0[i].z * sc; v0.w = a0[i].w * sc;
            v1.x = a1[i].x * sc; v1.y = a1[i].y * sc; v1.z = a1[i].z * sc; v1.w = a1[i].w * sc;
            uint2* h = (uint2*)g_hs2h + (size_t)grow * 16;
            h[2 * c] = pack_h4(v0);
            h[2 * c + 1] = pack_h4(v1);
        }
    }
}

extern "C" void kernel_launch(void* const* d_in, const int* in_sizes, int n_in,
                              void* d_out, int out_size) {
    const float* z   = (const float*)d_in[0];
    const int* ei    = (const int*)d_in[1];   // int32 OR int64 pairs (detected)
    const float* W1  = (const float*)d_in[2];
    const float* b1  = (const float*)d_in[3];
    const float* W2  = (const float*)d_in[4];
    const float* b2  = (const float*)d_in[5];
    float* out = (float*)d_out;

    k_init<<<(NN + 255) / 256, 256>>>(ei);
    k_hist<<<(NE / 4 + 255) / 256, 256>>>(ei);
    k_scan1<<<SCAN_NB, SCAN_B>>>();
    k_prep<<<NN * 16 / 256, 256>>>((const float4*)z);
    k_permute<<<(NE / 4 + 255) / 256, 256>>>(ei);
    k_gather<true><<<NN * 16 / 256, 256>>>(nullptr, nullptr);
    k_gemm<64, 128, 64, 1><<<(NN + 63) / 64, 256>>>(W1, b1);
    k_gemm<128, 64, 128, 2><<<(NN + 127) / 128, 256>>>(W2, nullptr);
    k_gather<false><<<NN * 16 / 256, 256>>>((float4*)out, (const float4*)b2);
}

// round 14
// speedup vs baseline: 1.2109x; 1.0111x over previous
#include <cuda_runtime.h>
#include <cuda_fp16.h>

#define NN 100000
#define NE 1600000
#define SCAN_B 1024
#define SCAN_NB ((NN + SCAN_B - 1) / SCAN_B)   // 98

// Scratch (static device globals — no dynamic allocation allowed)
__device__ uint2  g_zsh[NN * 16];   // z * dinv   [N,64] fp16
__device__ uint2  g_agg1h[NN * 16]; // (agg1 * dinv[dst]) [N,64] fp16 (gemm1-ready)
__device__ uint2  g_x1h[NN * 32];   // relu(gcn1) [N,128] fp16
__device__ uint2  g_hs2h[NN * 16];  // (x1@W2)*dinv [N,64] fp16
__device__ float  g_dinv[NN];
__device__ int    g_cnt[NN];        // in-degree (edges only)
__device__ int    g_off[NN];        // CSR row offsets (exclusive prefix of cnt)
__device__ int    g_cur[NN];        // mutable cursor for permute
__device__ int    g_esrc[NE];       // src indices sorted by dst
__device__ int    g_bsum[128];      // scan block sums (raw totals from scan1)
__device__ int    g_layout;         // 1 = int64 pairs, 0 = int32

__device__ __forceinline__ uint2 pack_h4(float4 v) {
    __half2 a = __floats2half2_rn(v.x, v.y);
    __half2 b = __floats2half2_rn(v.z, v.w);
    uint2 u;
    u.x = *(unsigned*)&a;
    u.y = *(unsigned*)&b;
    return u;
}
__device__ __forceinline__ float4 unpack_h4(uint2 u) {
    float2 f0 = __half22float2(*(__half2*)&u.x);
    float2 f1 = __half22float2(*(__half2*)&u.y);
    return make_float4(f0.x, f0.y, f1.x, f1.y);
}
__device__ __forceinline__ void acc_h4(float4& acc, uint2 u) {
    float2 f0 = __half22float2(*(__half2*)&u.x);
    float2 f1 = __half22float2(*(__half2*)&u.y);
    acc.x += f0.x; acc.y += f0.y; acc.z += f1.x; acc.w += f1.y;
}

// Fused: zero g_cnt + detect edge_index storage (block 0 does detection).
__global__ void k_init(const int* __restrict__ ei) {
    int i = blockIdx.x * 256 + threadIdx.x;
    if (i < NN) g_cnt[i] = 0;
    if (blockIdx.x == 0) {
        __shared__ int nz;
        if (threadIdx.x == 0) nz = 0;
        __syncthreads();
        if (ei[2 * threadIdx.x + 1] != 0) atomicOr(&nz, 1);
        __syncthreads();
        if (threadIdx.x == 0) g_layout = (nz == 0) ? 1 : 0;
    }
}

__device__ __forceinline__ int edge_src(const int* __restrict__ ei, int e, int layout) {
    return layout ? ei[2 * e] : ei[e];
}
__device__ __forceinline__ int edge_dst(const int* __restrict__ ei, int e, int layout) {
    return layout ? ei[2 * (NE + e)] : ei[NE + e];
}

// Histogram of destinations, 4 edges/thread via int4 (int32 path)
__global__ void k_hist(const int* __restrict__ ei) {
    int t = blockIdx.x * 256 + threadIdx.x;
    int e = t * 4;
    if (e >= NE) return;
    if (g_layout == 0) {
        int4 d4 = __ldg((const int4*)(ei + NE) + t);
        if ((unsigned)d4.x < NN) atomicAdd(&g_cnt[d4.x], 1);
        if ((unsigned)d4.y < NN) atomicAdd(&g_cnt[d4.y], 1);
        if ((unsigned)d4.z < NN) atomicAdd(&g_cnt[d4.z], 1);
        if ((unsigned)d4.w < NN) atomicAdd(&g_cnt[d4.w], 1);
    } else {
#pragma unroll
        for (int q = 0; q < 4; ++q) {
            int d = edge_dst(ei, e + q, 1);
            if ((unsigned)d < NN) atomicAdd(&g_cnt[d], 1);
        }
    }
}

// Block-level exclusive scan (Hillis-Steele), emits per-block totals.
__global__ void k_scan1() {
    __shared__ int sh[SCAN_B];
    int i = blockIdx.x * SCAN_B + threadIdx.x;
    int v = (i < NN) ? g_cnt[i] : 0;
    sh[threadIdx.x] = v;
    __syncthreads();
#pragma unroll
    for (int ofs = 1; ofs < SCAN_B; ofs <<= 1) {
        int t = (threadIdx.x >= ofs) ? sh[threadIdx.x - ofs] : 0;
        __syncthreads();
        sh[threadIdx.x] += t;
        __syncthreads();
    }
    if (i < NN) g_off[i] = sh[threadIdx.x] - v;   // exclusive
    if (threadIdx.x == SCAN_B - 1) g_bsum[blockIdx.x] = sh[SCAN_B - 1];
}

// Fused scan2 + scan3 + scale_init: each block re-scans the 98 block sums
// in smem, then NN*16 threads finalize offsets / dinv / zs (fp16).
__global__ void k_prep(const float4* __restrict__ z4) {
    __shared__ int bs[128];
    int t = threadIdx.x;
    if (t < 128) bs[t] = (t < SCAN_NB) ? g_bsum[t] : 0;
    __syncthreads();
    int v0 = (t < 128) ? bs[t] : 0;
#pragma unroll
    for (int ofs = 1; ofs < 128; ofs <<= 1) {
        int tv = (t < 128 && t >= ofs) ? bs[t - ofs] : 0;
        __syncthreads();
        if (t < 128) bs[t] += tv;
        __syncthreads();
    }
    if (t < 128) bs[t] -= v0;   // exclusive
    __syncthreads();

    int u = blockIdx.x * 256 + t;  // exactly NN*16
    int node = u >> 4;
    int f = u & 15;
    float dinv = rsqrtf((float)g_cnt[node] + 1.0f);
    if (f == 0) {
        int o = g_off[node] + bs[node >> 10];
        g_off[node] = o;
        g_cur[node] = o;
        g_dinv[node] = dinv;
    }
    float4 v = __ldg(z4 + u);
    v.x *= dinv; v.y *= dinv; v.z *= dinv; v.w *= dinv;
    g_zsh[u] = pack_h4(v);
}

// Counting-sort edges by destination, 4 edges/thread via int4 (int32 path)
__global__ void k_permute(const int* __restrict__ ei) {
    int t = blockIdx.x * 256 + threadIdx.x;
    int e = t * 4;
    if (e >= NE) return;
    if (g_layout == 0) {
        int4 s4 = __ldg((const int4*)ei + t);
        int4 d4 = __ldg((const int4*)(ei + NE) + t);
        if ((unsigned)s4.x < NN && (unsigned)d4.x < NN) g_esrc[atomicAdd(&g_cur[d4.x], 1)] = s4.x;
        if ((unsigned)s4.y < NN && (unsigned)d4.y < NN) g_esrc[atomicAdd(&g_cur[d4.y], 1)] = s4.y;
        if ((unsigned)s4.z < NN && (unsigned)d4.z < NN) g_esrc[atomicAdd(&g_cur[d4.z], 1)] = s4.z;
        if ((unsigned)s4.w < NN && (unsigned)d4.w < NN) g_esrc[atomicAdd(&g_cur[d4.w], 1)] = s4.w;
    } else {
#pragma unroll
        for (int q = 0; q < 4; ++q) {
            int s = edge_src(ei, e + q, 1);
            int d = edge_dst(ei, e + q, 1);
            if ((unsigned)s < NN && (unsigned)d < NN)
                g_esrc[atomicAdd(&g_cur[d], 1)] = s;
        }
    }
}

// Gather-side segment sum: 16 threads per node, one 4-feature column each.
// Payload rows are fp16; accumulation in fp32.
// FIRST: out = (sum including self-loop) * dinv[dst] as fp16 -> g_agg1h
// else : out = d_out = sum * dinv[dst] + b2 (fp32)
template <bool FIRST>
__global__ void k_gather(float4* __restrict__ dout, const float4* __restrict__ b2v) {
    int gt = blockIdx.x * 256 + threadIdx.x;  // exactly NN*16 threads
    int node = gt >> 4;
    int f = gt & 15;
    const uint2* hs = FIRST ? (const uint2*)g_zsh : (const uint2*)g_hs2h;
    float4 acc = make_float4(0.f, 0.f, 0.f, 0.f);
    acc_h4(acc, __ldg(hs + (size_t)node * 16 + f));  // self-loop seed
    int j = g_off[node];
    int end = j + g_cnt[node];
    for (; j + 4 <= end; j += 4) {
        int s0 = __ldg(&g_esrc[j]);
        int s1 = __ldg(&g_esrc[j + 1]);
        int s2 = __ldg(&g_esrc[j + 2]);
        int s3 = __ldg(&g_esrc[j + 3]);
        uint2 u0 = __ldg(hs + (size_t)s0 * 16 + f);
        uint2 u1 = __ldg(hs + (size_t)s1 * 16 + f);
        uint2 u2 = __ldg(hs + (size_t)s2 * 16 + f);
        uint2 u3 = __ldg(hs + (size_t)s3 * 16 + f);
        acc_h4(acc, u0); acc_h4(acc, u1); acc_h4(acc, u2); acc_h4(acc, u3);
    }
    for (; j < end; ++j) {
        int s0 = __ldg(&g_esrc[j]);
        acc_h4(acc, __ldg(hs + (size_t)s0 * 16 + f));
    }
    float sc = g_dinv[node];
    if (FIRST) {
        acc.x *= sc; acc.y *= sc; acc.z *= sc; acc.w *= sc;
        g_agg1h[(size_t)node * 16 + f] = pack_h4(acc);
    } else {
        float4 b = __ldg(b2v + f);
        acc.x = acc.x * sc + b.x; acc.y = acc.y * sc + b.y;
        acc.z = acc.z * sc + b.z; acc.w = acc.w * sc + b.w;
        dout[(size_t)node * 16 + f] = acc;
    }
}

// Dense GEMM: ROWS rows/block, 256 threads, R=4 rows/thread, float4 zk loads.
// Inputs are fp16 rows (converted at staging); math stays fp32 FFMA.
// EPI==1: in = g_agg1h (pre-scaled), out = relu(acc + b1) fp16 -> g_x1h
// EPI==2: in = g_x1h,  out = (acc * dinv[row]) fp16 -> g_hs2h
template <int K, int N, int ROWS, int EPI>
__global__ void __launch_bounds__(256) k_gemm(const float* __restrict__ W,
                                              const float* __restrict__ bias) {
    constexpr int TPR = N / 8;          // threads per row-group (8 outputs each)
    constexpr int GROUPS = 256 / TPR;   // row groups per block
    constexpr int R = ROWS / GROUPS;    // rows per thread (4)
    constexpr int KT = 32;
    constexpr int RST = KT + 4;         // float stride, keeps float4 alignment

    __shared__ __align__(16) float Ws[KT * N];
    __shared__ __align__(16) float Rs[ROWS * RST];

    const uint2* in = (EPI == 1) ? (const uint2*)g_agg1h : (const uint2*)g_x1h;
    constexpr int ROW_U2 = K / 4;       // uint2 per input row

    int tid = threadIdx.x;
    int c = tid % TPR;
    int g = tid / TPR;
    int row0 = blockIdx.x * ROWS;

    float4 a0[R], a1[R];
#pragma unroll
    for (int i = 0; i < R; i++) {
        a0[i] = make_float4(0.f, 0.f, 0.f, 0.f);
        a1[i] = make_float4(0.f, 0.f, 0.f, 0.f);
    }

#pragma unroll
    for (int kt = 0; kt < K / KT; ++kt) {
        const float4* Wg = (const float4*)(W + kt * KT * N);
        float4* Ws4 = (float4*)Ws;
#pragma unroll
        for (int j = tid; j < KT * N / 4; j += 256) Ws4[j] = __ldg(Wg + j);
#pragma unroll
        for (int j = tid; j < ROWS * (KT / 4); j += 256) {
            int r = j / (KT / 4), c4 = j % (KT / 4);
            int grow = row0 + r;
            if (grow >= NN) grow = NN - 1;
            uint2 u = __ldg(in + (size_t)grow * ROW_U2 + kt * (KT / 4) + c4);
            *(float4*)&Rs[r * RST + c4 * 4] = unpack_h4(u);
        }
        __syncthreads();

        const float4* Wr = (const float4*)Ws;
#pragma unroll
        for (int kk4 = 0; kk4 < KT / 4; ++kk4) {
            float4 zk[R];
#pragma unroll
            for (int i = 0; i < R; ++i)
                zk[i] = *(const float4*)&Rs[(g * R + i) * RST + kk4 * 4];
#pragma unroll
            for (int kc = 0; kc < 4; ++kc) {
                float4 w0 = Wr[(kk4 * 4 + kc) * (N / 4) + 2 * c];
                float4 w1 = Wr[(kk4 * 4 + kc) * (N / 4) + 2 * c + 1];
#pragma unroll
                for (int i = 0; i < R; ++i) {
                    float z = (kc == 0) ? zk[i].x : (kc == 1) ? zk[i].y
                             : (kc == 2) ? zk[i].z : zk[i].w;
                    a0[i].x += z * w0.x; a0[i].y += z * w0.y;
                    a0[i].z += z * w0.z; a0[i].w += z * w0.w;
                    a1[i].x += z * w1.x; a1[i].y += z * w1.y;
                    a1[i].z += z * w1.z; a1[i].w += z * w1.w;
                }
            }
        }
        __syncthreads();
    }

#pragma unroll
    for (int i = 0; i < R; ++i) {
        int grow = row0 + g * R + i;
        if (grow >= NN) continue;
        if (EPI == 1) {
            float4 bb0 = __ldg((const float4*)bias + 2 * c);
            float4 bb1 = __ldg((const float4*)bias + 2 * c + 1);
            float4 v0, v1;
            v0.x = fmaxf(a0[i].x + bb0.x, 0.f); v0.y = fmaxf(a0[i].y + bb0.y, 0.f);
            v0.z = fmaxf(a0[i].z + bb0.z, 0.f); v0.w = fmaxf(a0[i].w + bb0.w, 0.f);
            v1.x = fmaxf(a1[i].x + bb1.x, 0.f); v1.y = fmaxf(a1[i].y + bb1.y, 0.f);
            v1.z = fmaxf(a1[i].z + bb1.z, 0.f); v1.w = fmaxf(a1[i].w + bb1.w, 0.f);
            uint2* op = (uint2*)g_x1h + (size_t)grow * (N / 4);
            op[2 * c] = pack_h4(v0);
            op[2 * c + 1] = pack_h4(v1);
        } else {
            float sc = g_dinv[grow];
            float4 v0, v1;
            v0.x = a0[i].x * sc; v0.y = a0[i].y * sc; v0.z = a0[i].z * sc; v0.w = a0[i].w * sc;
            v1.x = a1[i].x * sc; v1.y = a1[i].y * sc; v1.z = a1[i].z * sc; v1.w = a1[i].w * sc;
            uint2* h = (uint2*)g_hs2h + (size_t)grow * (N / 4);
            h[2 * c] = pack_h4(v0);
            h[2 * c + 1] = pack_h4(v1);
        }
    }
}

extern "C" void kernel_launch(void* const* d_in, const int* in_sizes, int n_in,
                              void* d_out, int out_size) {
    const float* z   = (const float*)d_in[0];
    const int* ei    = (const int*)d_in[1];   // int32 OR int64 pairs (detected)
    const float* W1  = (const float*)d_in[2];
    const float* b1  = (const float*)d_in[3];
    const float* W2  = (const float*)d_in[4];
    const float* b2  = (const float*)d_in[5];
    float* out = (float*)d_out;

    k_init<<<(NN + 255) / 256, 256>>>(ei);
    k_hist<<<(NE / 4 + 255) / 256, 256>>>(ei);
    k_scan1<<<SCAN_NB, SCAN_B>>>();
    k_prep<<<NN * 16 / 256, 256>>>((const float4*)z);
    k_permute<<<(NE / 4 + 255) / 256, 256>>>(ei);
    k_gather<true><<<NN * 16 / 256, 256>>>(nullptr, nullptr);
    k_gemm<64, 128, 64, 1><<<(NN + 63) / 64, 256>>>(W1, b1);
    k_gemm<128, 64, 128, 2><<<(NN + 127) / 128, 256>>>(W2, nullptr);
    k_gather<false><<<NN * 16 / 256, 256>>>((float4*)out, (const float4*)b2);
}

// round 15
// speedup vs baseline: 2.1408x; 1.7680x over previous
#include <cuda_runtime.h>
#include <cuda_fp16.h>
#include <mma.h>

#define NN 100000
#define NPAD (NN + 64)
#define NE 1600000
#define SCAN_B 1024
#define SCAN_NB ((NN + SCAN_B - 1) / SCAN_B)   // 98

// Scratch (static device globals — zero-initialized; padded +64 rows for wmma)
__device__ uint2  g_zsh[NN * 16];     // z * dinv   [N,64] fp16
__device__ uint2  g_agg1h[NPAD * 16]; // (agg1 * dinv[dst]) [N,64] fp16 (gemm1-ready)
__device__ uint2  g_x1h[NPAD * 32];   // relu(gcn1) [N,128] fp16
__device__ uint2  g_hs2h[NPAD * 16];  // (x1@W2)*dinv [N,64] fp16
__device__ float  g_dinv[NPAD];
__device__ int    g_cnt[NN];        // in-degree (edges only)
__device__ int    g_off[NN];        // CSR row offsets (exclusive prefix of cnt)
__device__ int    g_cur[NN];        // mutable cursor for permute
__device__ int    g_esrc[NE];       // src indices sorted by dst
__device__ int    g_bsum[128];      // scan block sums (raw totals from scan1)
__device__ int    g_layout;         // 1 = int64 pairs, 0 = int32

__device__ __forceinline__ uint2 pack_h4(float4 v) {
    __half2 a = __floats2half2_rn(v.x, v.y);
    __half2 b = __floats2half2_rn(v.z, v.w);
    uint2 u;
    u.x = *(unsigned*)&a;
    u.y = *(unsigned*)&b;
    return u;
}
__device__ __forceinline__ void acc_h4(float4& acc, uint2 u) {
    float2 f0 = __half22float2(*(__half2*)&u.x);
    float2 f1 = __half22float2(*(__half2*)&u.y);
    acc.x += f0.x; acc.y += f0.y; acc.z += f1.x; acc.w += f1.y;
}

// Fused: zero g_cnt + detect edge_index storage (block 0 does detection).
__global__ void k_init(const int* __restrict__ ei) {
    int i = blockIdx.x * 256 + threadIdx.x;
    if (i < NN) g_cnt[i] = 0;
    if (blockIdx.x == 0) {
        __shared__ int nz;
        if (threadIdx.x == 0) nz = 0;
        __syncthreads();
        if (ei[2 * threadIdx.x + 1] != 0) atomicOr(&nz, 1);
        __syncthreads();
        if (threadIdx.x == 0) g_layout = (nz == 0) ? 1 : 0;
    }
}

__device__ __forceinline__ int edge_src(const int* __restrict__ ei, int e, int layout) {
    return layout ? ei[2 * e] : ei[e];
}
__device__ __forceinline__ int edge_dst(const int* __restrict__ ei, int e, int layout) {
    return layout ? ei[2 * (NE + e)] : ei[NE + e];
}

// Histogram of destinations, 4 edges/thread via int4 (int32 path)
__global__ void k_hist(const int* __restrict__ ei) {
    int t = blockIdx.x * 256 + threadIdx.x;
    int e = t * 4;
    if (e >= NE) return;
    if (g_layout == 0) {
        int4 d4 = __ldg((const int4*)(ei + NE) + t);
        if ((unsigned)d4.x < NN) atomicAdd(&g_cnt[d4.x], 1);
        if ((unsigned)d4.y < NN) atomicAdd(&g_cnt[d4.y], 1);
        if ((unsigned)d4.z < NN) atomicAdd(&g_cnt[d4.z], 1);
        if ((unsigned)d4.w < NN) atomicAdd(&g_cnt[d4.w], 1);
    } else {
#pragma unroll
        for (int q = 0; q < 4; ++q) {
            int d = edge_dst(ei, e + q, 1);
            if ((unsigned)d < NN) atomicAdd(&g_cnt[d], 1);
        }
    }
}

// Block-level exclusive scan (Hillis-Steele), emits per-block totals.
__global__ void k_scan1() {
    __shared__ int sh[SCAN_B];
    int i = blockIdx.x * SCAN_B + threadIdx.x;
    int v = (i < NN) ? g_cnt[i] : 0;
    sh[threadIdx.x] = v;
    __syncthreads();
#pragma unroll
    for (int ofs = 1; ofs < SCAN_B; ofs <<= 1) {
        int t = (threadIdx.x >= ofs) ? sh[threadIdx.x - ofs] : 0;
        __syncthreads();
        sh[threadIdx.x] += t;
        __syncthreads();
    }
    if (i < NN) g_off[i] = sh[threadIdx.x] - v;   // exclusive
    if (threadIdx.x == SCAN_B - 1) g_bsum[blockIdx.x] = sh[SCAN_B - 1];
}

// Fused scan2 + scan3 + scale_init: each block re-scans the 98 block sums
// in smem, then NN*16 threads finalize offsets / dinv / zs (fp16).
__global__ void k_prep(const float4* __restrict__ z4) {
    __shared__ int bs[128];
    int t = threadIdx.x;
    if (t < 128) bs[t] = (t < SCAN_NB) ? g_bsum[t] : 0;
    __syncthreads();
    int v0 = (t < 128) ? bs[t] : 0;
#pragma unroll
    for (int ofs = 1; ofs < 128; ofs <<= 1) {
        int tv = (t < 128 && t >= ofs) ? bs[t - ofs] : 0;
        __syncthreads();
        if (t < 128) bs[t] += tv;
        __syncthreads();
    }
    if (t < 128) bs[t] -= v0;   // exclusive
    __syncthreads();

    int u = blockIdx.x * 256 + t;  // exactly NN*16
    int node = u >> 4;
    int f = u & 15;
    float dinv = rsqrtf((float)g_cnt[node] + 1.0f);
    if (f == 0) {
        int o = g_off[node] + bs[node >> 10];
        g_off[node] = o;
        g_cur[node] = o;
        g_dinv[node] = dinv;
    }
    float4 v = __ldg(z4 + u);
    v.x *= dinv; v.y *= dinv; v.z *= dinv; v.w *= dinv;
    g_zsh[u] = pack_h4(v);
}

// Counting-sort edges by destination, 4 edges/thread via int4 (int32 path)
__global__ void k_permute(const int* __restrict__ ei) {
    int t = blockIdx.x * 256 + threadIdx.x;
    int e = t * 4;
    if (e >= NE) return;
    if (g_layout == 0) {
        int4 s4 = __ldg((const int4*)ei + t);
        int4 d4 = __ldg((const int4*)(ei + NE) + t);
        if ((unsigned)s4.x < NN && (unsigned)d4.x < NN) g_esrc[atomicAdd(&g_cur[d4.x], 1)] = s4.x;
        if ((unsigned)s4.y < NN && (unsigned)d4.y < NN) g_esrc[atomicAdd(&g_cur[d4.y], 1)] = s4.y;
        if ((unsigned)s4.z < NN && (unsigned)d4.z < NN) g_esrc[atomicAdd(&g_cur[d4.z], 1)] = s4.z;
        if ((unsigned)s4.w < NN && (unsigned)d4.w < NN) g_esrc[atomicAdd(&g_cur[d4.w], 1)] = s4.w;
    } else {
#pragma unroll
        for (int q = 0; q < 4; ++q) {
            int s = edge_src(ei, e + q, 1);
            int d = edge_dst(ei, e + q, 1);
            if ((unsigned)s < NN && (unsigned)d < NN)
                g_esrc[atomicAdd(&g_cur[d], 1)] = s;
        }
    }
}

// Gather-side segment sum: 16 threads per node, one 4-feature column each.
// FIRST: out = (sum incl self-loop) * dinv[dst] fp16 -> g_agg1h (gemm1-ready)
// else : out = d_out = sum * dinv[dst] + b2 (fp32)
template <bool FIRST>
__global__ void k_gather(float4* __restrict__ dout, const float4* __restrict__ b2v) {
    int gt = blockIdx.x * 256 + threadIdx.x;  // exactly NN*16 threads
    int node = gt >> 4;
    int f = gt & 15;
    const uint2* hs = FIRST ? (const uint2*)g_zsh : (const uint2*)g_hs2h;
    float4 acc = make_float4(0.f, 0.f, 0.f, 0.f);
    acc_h4(acc, __ldg(hs + (size_t)node * 16 + f));  // self-loop seed
    int j = g_off[node];
    int end = j + g_cnt[node];
    for (; j + 4 <= end; j += 4) {
        int s0 = __ldg(&g_esrc[j]);
        int s1 = __ldg(&g_esrc[j + 1]);
        int s2 = __ldg(&g_esrc[j + 2]);
        int s3 = __ldg(&g_esrc[j + 3]);
        uint2 u0 = __ldg(hs + (size_t)s0 * 16 + f);
        uint2 u1 = __ldg(hs + (size_t)s1 * 16 + f);
        uint2 u2 = __ldg(hs + (size_t)s2 * 16 + f);
        uint2 u3 = __ldg(hs + (size_t)s3 * 16 + f);
        acc_h4(acc, u0); acc_h4(acc, u1); acc_h4(acc, u2); acc_h4(acc, u3);
    }
    for (; j < end; ++j) {
        int s0 = __ldg(&g_esrc[j]);
        acc_h4(acc, __ldg(hs + (size_t)s0 * 16 + f));
    }
    float sc = g_dinv[node];
    if (FIRST) {
        acc.x *= sc; acc.y *= sc; acc.z *= sc; acc.w *= sc;
        g_agg1h[(size_t)node * 16 + f] = pack_h4(acc);
    } else {
        float4 b = __ldg(b2v + f);
        acc.x = acc.x * sc + b.x; acc.y = acc.y * sc + b.y;
        acc.z = acc.z * sc + b.z; acc.w = acc.w * sc + b.w;
        dout[(size_t)node * 16 + f] = acc;
    }
}

// Tensor-core GEMM via wmma HMMA: 64 rows/block, 256 threads (8 warps).
// A fp16 (raw copy from fp16 intermediates), W converted fp32->fp16 at staging,
// fp32 accumulate. Epilogue through reused smem.
// EPI==1: in=g_agg1h [*,64],  out=relu(acc+b1) fp16 -> g_x1h   (N=128)
// EPI==2: in=g_x1h   [*,128], out=(acc*dinv) fp16 -> g_hs2h    (N=64)
template <int K, int N, int EPI>
__global__ void __launch_bounds__(256) k_gemm_wmma(const float* __restrict__ W,
                                                   const float* __restrict__ bias) {
    using namespace nvcuda;
    constexpr int AW = K + 8;          // A smem ld (halves)
    constexpr int BW = N + 8;          // B smem ld (halves)
    constexpr int CW = N + 8;          // C smem ld (floats)
    constexpr int CT = N / 32;         // accum col-tiles per warp (4 or 2)
    constexpr size_t SZ_AB = (size_t)64 * AW * 2 + (size_t)K * BW * 2;
    constexpr size_t SZ_C  = (size_t)64 * CW * 4;
    constexpr size_t SZ = SZ_AB > SZ_C ? SZ_AB : SZ_C;

    __shared__ __align__(16) char smraw[SZ];
    __half* As = (__half*)smraw;
    __half* Bs = As + 64 * AW;
    float*  Cs = (float*)smraw;

    const uint2* in = (EPI == 1) ? (const uint2*)g_agg1h : (const uint2*)g_x1h;
    int tid = threadIdx.x;
    int row0 = blockIdx.x * 64;

    // Stage A: raw fp16 copy (uint2 = 4 halves). Padded rows read zero-init data.
#pragma unroll
    for (int j = tid; j < 64 * (K / 4); j += 256) {
        int r = j / (K / 4), c4 = j % (K / 4);
        uint2 u = __ldg(in + (size_t)(row0 + r) * (K / 4) + c4);
        *(uint2*)&As[r * AW + c4 * 4] = u;
    }
    // Stage B: convert W fp32 -> fp16
#pragma unroll
    for (int j = tid; j < K * (N / 4); j += 256) {
        int r = j / (N / 4), c4 = j % (N / 4);
        float4 w = __ldg((const float4*)W + j);
        *(uint2*)&Bs[r * BW + c4 * 4] = pack_h4(w);
    }
    __syncthreads();

    int w = tid >> 5;
    int rt = w & 3;                    // row tile (16 rows each)
    int ch = w >> 2;                   // column half (0/1)
    int col_base = ch * (N / 2);

    wmma::fragment<wmma::accumulator, 16, 16, 16, float> acc[CT];
#pragma unroll
    for (int t = 0; t < CT; ++t) wmma::fill_fragment(acc[t], 0.0f);

#pragma unroll
    for (int k0 = 0; k0 < K / 16; ++k0) {
        wmma::fragment<wmma::matrix_a, 16, 16, 16, __half, wmma::row_major> fa;
        wmma::load_matrix_sync(fa, As + rt * 16 * AW + k0 * 16, AW);
#pragma unroll
        for (int t = 0; t < CT; ++t) {
            wmma::fragment<wmma::matrix_b, 16, 16, 16, __half, wmma::row_major> fb;
            wmma::load_matrix_sync(fb, Bs + (k0 * 16) * BW + col_base + t * 16, BW);
            wmma::mma_sync(acc[t], fa, fb, acc[t]);
        }
    }
    __syncthreads();   // done reading As/Bs; reuse smem as Cs

#pragma unroll
    for (int t = 0; t < CT; ++t)
        wmma::store_matrix_sync(Cs + rt * 16 * CW + col_base + t * 16, acc[t], CW,
                                wmma::mem_row_major);
    __syncthreads();

    // Epilogue: smem fp32 -> global fp16 (buffers padded; unconditional writes)
#pragma unroll
    for (int j = tid; j < 64 * (N / 4); j += 256) {
        int r = j / (N / 4), c4 = j % (N / 4);
        float4 v = *(float4*)&Cs[r * CW + c4 * 4];
        if (EPI == 1) {
            float4 b = __ldg((const float4*)bias + c4);
            v.x = fmaxf(v.x + b.x, 0.f); v.y = fmaxf(v.y + b.y, 0.f);
            v.z = fmaxf(v.z + b.z, 0.f); v.w = fmaxf(v.w + b.w, 0.f);
            g_x1h[(size_t)(row0 + r) * 32 + c4] = pack_h4(v);
        } else {
            float sc = g_dinv[row0 + r];
            v.x *= sc; v.y *= sc; v.z *= sc; v.w *= sc;
            g_hs2h[(size_t)(row0 + r) * 16 + c4] = pack_h4(v);
        }
    }
}

extern "C" void kernel_launch(void* const* d_in, const int* in_sizes, int n_in,
                              void* d_out, int out_size) {
    const float* z   = (const float*)d_in[0];
    const int* ei    = (const int*)d_in[1];   // int32 OR int64 pairs (detected)
    const float* W1  = (const float*)d_in[2];
    const float* b1  = (const float*)d_in[3];
    const float* W2  = (const float*)d_in[4];
    const float* b2  = (const float*)d_in[5];
    float* out = (float*)d_out;

    k_init<<<(NN + 255) / 256, 256>>>(ei);
    k_hist<<<(NE / 4 + 255) / 256, 256>>>(ei);
    k_scan1<<<SCAN_NB, SCAN_B>>>();
    k_prep<<<NN * 16 / 256, 256>>>((const float4*)z);
    k_permute<<<(NE / 4 + 255) / 256, 256>>>(ei);
    k_gather<true><<<NN * 16 / 256, 256>>>(nullptr, nullptr);
    k_gemm_wmma<64, 128, 1><<<(NN + 63) / 64, 256>>>(W1, b1);
    k_gemm_wmma<128, 64, 2><<<(NN + 63) / 64, 256>>>(W2, nullptr);
    k_gather<false><<<NN * 16 / 256, 256>>>((float4*)out, (const float4*)b2);
}

// round 16
// speedup vs baseline: 2.1489x; 1.0038x over previous
#include <cuda_runtime.h>
#include <cuda_fp16.h>
#include <mma.h>

#define NN 100000
#define NPAD (NN + 64)
#define NE 1600000
#define SCAN_B 1024
#define SCAN_NB ((NN + SCAN_B - 1) / SCAN_B)   // 98

// Scratch (static device globals — zero-initialized; padded +64 rows for wmma)
__device__ uint2  g_zsh[NN * 16];     // z * dinv   [N,64] fp16
__device__ uint2  g_agg1h[NPAD * 16]; // (agg1 * dinv[dst]) [N,64] fp16 (gemm1-ready)
__device__ uint2  g_x1h[NPAD * 32];   // relu(gcn1) [N,128] fp16
__device__ uint2  g_hs2h[NPAD * 16];  // (x1@W2)*dinv [N,64] fp16
__device__ float  g_dinv[NPAD];
__device__ int    g_cnt[NN];        // in-degree (edges only)
__device__ int    g_off[NN];        // CSR row offsets (exclusive prefix of cnt)
__device__ int    g_cur[NN];        // mutable cursor for permute
__device__ int    g_esrc[NE];       // src indices sorted by dst
__device__ int    g_bsum[128];      // scan block sums (raw totals from scan1)
__device__ int    g_layout;         // 1 = int64 pairs, 0 = int32

__device__ __forceinline__ uint2 pack_h4(float4 v) {
    __half2 a = __floats2half2_rn(v.x, v.y);
    __half2 b = __floats2half2_rn(v.z, v.w);
    uint2 u;
    u.x = *(unsigned*)&a;
    u.y = *(unsigned*)&b;
    return u;
}
__device__ __forceinline__ void acc_h4(float4& acc, uint2 u) {
    float2 f0 = __half22float2(*(__half2*)&u.x);
    float2 f1 = __half22float2(*(__half2*)&u.y);
    acc.x += f0.x; acc.y += f0.y; acc.z += f1.x; acc.w += f1.y;
}

// Detection only (g_cnt zeroing moved to cudaMemsetAsync).
__global__ void k_detect(const int* __restrict__ ei) {
    __shared__ int nz;
    if (threadIdx.x == 0) nz = 0;
    __syncthreads();
    if (ei[2 * threadIdx.x + 1] != 0) atomicOr(&nz, 1);
    __syncthreads();
    if (threadIdx.x == 0) g_layout = (nz == 0) ? 1 : 0;
}

__device__ __forceinline__ int edge_src(const int* __restrict__ ei, int e, int layout) {
    return layout ? ei[2 * e] : ei[e];
}
__device__ __forceinline__ int edge_dst(const int* __restrict__ ei, int e, int layout) {
    return layout ? ei[2 * (NE + e)] : ei[NE + e];
}

// Histogram of destinations, 4 edges/thread via int4 (int32 path)
__global__ void k_hist(const int* __restrict__ ei) {
    int t = blockIdx.x * 256 + threadIdx.x;
    int e = t * 4;
    if (e >= NE) return;
    if (g_layout == 0) {
        int4 d4 = __ldg((const int4*)(ei + NE) + t);
        if ((unsigned)d4.x < NN) atomicAdd(&g_cnt[d4.x], 1);
        if ((unsigned)d4.y < NN) atomicAdd(&g_cnt[d4.y], 1);
        if ((unsigned)d4.z < NN) atomicAdd(&g_cnt[d4.z], 1);
        if ((unsigned)d4.w < NN) atomicAdd(&g_cnt[d4.w], 1);
    } else {
#pragma unroll
        for (int q = 0; q < 4; ++q) {
            int d = edge_dst(ei, e + q, 1);
            if ((unsigned)d < NN) atomicAdd(&g_cnt[d], 1);
        }
    }
}

// Block-level exclusive scan (Hillis-Steele), emits per-block totals.
__global__ void k_scan1() {
    __shared__ int sh[SCAN_B];
    int i = blockIdx.x * SCAN_B + threadIdx.x;
    int v = (i < NN) ? g_cnt[i] : 0;
    sh[threadIdx.x] = v;
    __syncthreads();
#pragma unroll
    for (int ofs = 1; ofs < SCAN_B; ofs <<= 1) {
        int t = (threadIdx.x >= ofs) ? sh[threadIdx.x - ofs] : 0;
        __syncthreads();
        sh[threadIdx.x] += t;
        __syncthreads();
    }
    if (i < NN) g_off[i] = sh[threadIdx.x] - v;   // exclusive
    if (threadIdx.x == SCAN_B - 1) g_bsum[blockIdx.x] = sh[SCAN_B - 1];
}

// Fused scan2 + scan3 + scale_init. 2 units (uint2 columns) per thread.
__global__ void k_prep(const float4* __restrict__ z4) {
    __shared__ int bs[128];
    int t = threadIdx.x;
    if (t < 128) bs[t] = (t < SCAN_NB) ? g_bsum[t] : 0;
    __syncthreads();
    int v0 = (t < 128) ? bs[t] : 0;
#pragma unroll
    for (int ofs = 1; ofs < 128; ofs <<= 1) {
        int tv = (t < 128 && t >= ofs) ? bs[t - ofs] : 0;
        __syncthreads();
        if (t < 128) bs[t] += tv;
        __syncthreads();
    }
    if (t < 128) bs[t] -= v0;   // exclusive
    __syncthreads();

    int u0 = (blockIdx.x * 256 + t) * 2;   // exactly NN*16 units total
#pragma unroll
    for (int q = 0; q < 2; ++q) {
        int u = u0 + q;
        int node = u >> 4;
        int f = u & 15;
        float dinv = rsqrtf((float)g_cnt[node] + 1.0f);
        if (f == 0) {
            int o = g_off[node] + bs[node >> 10];
            g_off[node] = o;
            g_cur[node] = o;
            g_dinv[node] = dinv;
        }
        float4 v = __ldg(z4 + u);
        v.x *= dinv; v.y *= dinv; v.z *= dinv; v.w *= dinv;
        g_zsh[u] = pack_h4(v);
    }
}

// Counting-sort edges by destination, 4 edges/thread via int4 (int32 path)
__global__ void k_permute(const int* __restrict__ ei) {
    int t = blockIdx.x * 256 + threadIdx.x;
    int e = t * 4;
    if (e >= NE) return;
    if (g_layout == 0) {
        int4 s4 = __ldg((const int4*)ei + t);
        int4 d4 = __ldg((const int4*)(ei + NE) + t);
        if ((unsigned)s4.x < NN && (unsigned)d4.x < NN) g_esrc[atomicAdd(&g_cur[d4.x], 1)] = s4.x;
        if ((unsigned)s4.y < NN && (unsigned)d4.y < NN) g_esrc[atomicAdd(&g_cur[d4.y], 1)] = s4.y;
        if ((unsigned)s4.z < NN && (unsigned)d4.z < NN) g_esrc[atomicAdd(&g_cur[d4.z], 1)] = s4.z;
        if ((unsigned)s4.w < NN && (unsigned)d4.w < NN) g_esrc[atomicAdd(&g_cur[d4.w], 1)] = s4.w;
    } else {
#pragma unroll
        for (int q = 0; q < 4; ++q) {
            int s = edge_src(ei, e + q, 1);
            int d = edge_dst(ei, e + q, 1);
            if ((unsigned)s < NN && (unsigned)d < NN)
                g_esrc[atomicAdd(&g_cur[d], 1)] = s;
        }
    }
}

// Gather-side segment sum: 16 threads per node, one 4-feature column each.
// 8-way + 4-way + scalar unroll for MLP. fp16 payload, fp32 accumulate.
// FIRST: out = (sum incl self-loop) * dinv[dst] fp16 -> g_agg1h (gemm1-ready)
// else : out = d_out = sum * dinv[dst] + b2 (fp32)
template <bool FIRST>
__global__ void k_gather(float4* __restrict__ dout, const float4* __restrict__ b2v) {
    int gt = blockIdx.x * 256 + threadIdx.x;  // exactly NN*16 threads
    int node = gt >> 4;
    int f = gt & 15;
    const uint2* hs = FIRST ? (const uint2*)g_zsh : (const uint2*)g_hs2h;
    float4 acc = make_float4(0.f, 0.f, 0.f, 0.f);
    acc_h4(acc, __ldg(hs + (size_t)node * 16 + f));  // self-loop seed
    int j = g_off[node];
    int end = j + g_cnt[node];
    for (; j + 8 <= end; j += 8) {
        int s0 = __ldg(&g_esrc[j]);
        int s1 = __ldg(&g_esrc[j + 1]);
        int s2 = __ldg(&g_esrc[j + 2]);
        int s3 = __ldg(&g_esrc[j + 3]);
        int s4 = __ldg(&g_esrc[j + 4]);
        int s5 = __ldg(&g_esrc[j + 5]);
        int s6 = __ldg(&g_esrc[j + 6]);
        int s7 = __ldg(&g_esrc[j + 7]);
        uint2 u0 = __ldg(hs + (size_t)s0 * 16 + f);
        uint2 u1 = __ldg(hs + (size_t)s1 * 16 + f);
        uint2 u2 = __ldg(hs + (size_t)s2 * 16 + f);
        uint2 u3 = __ldg(hs + (size_t)s3 * 16 + f);
        uint2 u4 = __ldg(hs + (size_t)s4 * 16 + f);
        uint2 u5 = __ldg(hs + (size_t)s5 * 16 + f);
        uint2 u6 = __ldg(hs + (size_t)s6 * 16 + f);
        uint2 u7 = __ldg(hs + (size_t)s7 * 16 + f);
        acc_h4(acc, u0); acc_h4(acc, u1); acc_h4(acc, u2); acc_h4(acc, u3);
        acc_h4(acc, u4); acc_h4(acc, u5); acc_h4(acc, u6); acc_h4(acc, u7);
    }
    if (j + 4 <= end) {
        int s0 = __ldg(&g_esrc[j]);
        int s1 = __ldg(&g_esrc[j + 1]);
        int s2 = __ldg(&g_esrc[j + 2]);
        int s3 = __ldg(&g_esrc[j + 3]);
        uint2 u0 = __ldg(hs + (size_t)s0 * 16 + f);
        uint2 u1 = __ldg(hs + (size_t)s1 * 16 + f);
        uint2 u2 = __ldg(hs + (size_t)s2 * 16 + f);
        uint2 u3 = __ldg(hs + (size_t)s3 * 16 + f);
        acc_h4(acc, u0); acc_h4(acc, u1); acc_h4(acc, u2); acc_h4(acc, u3);
        j += 4;
    }
    for (; j < end; ++j) {
        int s0 = __ldg(&g_esrc[j]);
        acc_h4(acc, __ldg(hs + (size_t)s0 * 16 + f));
    }
    float sc = g_dinv[node];
    if (FIRST) {
        acc.x *= sc; acc.y *= sc; acc.z *= sc; acc.w *= sc;
        g_agg1h[(size_t)node * 16 + f] = pack_h4(acc);
    } else {
        float4 b = __ldg(b2v + f);
        acc.x = acc.x * sc + b.x; acc.y = acc.y * sc + b.y;
        acc.z = acc.z * sc + b.z; acc.w = acc.w * sc + b.w;
        dout[(size_t)node * 16 + f] = acc;
    }
}

// Tensor-core GEMM via wmma HMMA: 64 rows/block, 256 threads (8 warps).
// A fp16 (raw copy), W converted fp32->fp16 at staging, fp32 accumulate.
// EPI==1: in=g_agg1h [*,64],  out=relu(acc+b1) fp16 -> g_x1h   (N=128)
// EPI==2: in=g_x1h   [*,128], out=(acc*dinv) fp16 -> g_hs2h    (N=64)
template <int K, int N, int EPI>
__global__ void __launch_bounds__(256) k_gemm_wmma(const float* __restrict__ W,
                                                   const float* __restrict__ bias) {
    using namespace nvcuda;
    constexpr int AW = K + 8;          // A smem ld (halves)
    constexpr int BW = N + 8;          // B smem ld (halves)
    constexpr int CW = N + 8;          // C smem ld (floats)
    constexpr int CT = N / 32;         // accum col-tiles per warp (4 or 2)
    constexpr size_t SZ_AB = (size_t)64 * AW * 2 + (size_t)K * BW * 2;
    constexpr size_t SZ_C  = (size_t)64 * CW * 4;
    constexpr size_t SZ = SZ_AB > SZ_C ? SZ_AB : SZ_C;

    __shared__ __align__(16) char smraw[SZ];
    __half* As = (__half*)smraw;
    __half* Bs = As + 64 * AW;
    float*  Cs = (float*)smraw;

    const uint2* in = (EPI == 1) ? (const uint2*)g_agg1h : (const uint2*)g_x1h;
    int tid = threadIdx.x;
    int row0 = blockIdx.x * 64;

    // Stage A: raw fp16 copy (uint2 = 4 halves). Padded rows read zero-init data.
#pragma unroll
    for (int j = tid; j < 64 * (K / 4); j += 256) {
        int r = j / (K / 4), c4 = j % (K / 4);
        uint2 u = __ldg(in + (size_t)(row0 + r) * (K / 4) + c4);
        *(uint2*)&As[r * AW + c4 * 4] = u;
    }
    // Stage B: convert W fp32 -> fp16
#pragma unroll
    for (int j = tid; j < K * (N / 4); j += 256) {
        int r = j / (N / 4), c4 = j % (N / 4);
        float4 w = __ldg((const float4*)W + j);
        *(uint2*)&Bs[r * BW + c4 * 4] = pack_h4(w);
    }
    __syncthreads();

    int w = tid >> 5;
    int rt = w & 3;                    // row tile (16 rows each)
    int ch = w >> 2;                   // column half (0/1)
    int col_base = ch * (N / 2);

    wmma::fragment<wmma::accumulator, 16, 16, 16, float> acc[CT];
#pragma unroll
    for (int t = 0; t < CT; ++t) wmma::fill_fragment(acc[t], 0.0f);

#pragma unroll
    for (int k0 = 0; k0 < K / 16; ++k0) {
        wmma::fragment<wmma::matrix_a, 16, 16, 16, __half, wmma::row_major> fa;
        wmma::load_matrix_sync(fa, As + rt * 16 * AW + k0 * 16, AW);
#pragma unroll
        for (int t = 0; t < CT; ++t) {
            wmma::fragment<wmma::matrix_b, 16, 16, 16, __half, wmma::row_major> fb;
            wmma::load_matrix_sync(fb, Bs + (k0 * 16) * BW + col_base + t * 16, BW);
            wmma::mma_sync(acc[t], fa, fb, acc[t]);
        }
    }
    __syncthreads();   // done reading As/Bs; reuse smem as Cs

#pragma unroll
    for (int t = 0; t < CT; ++t)
        wmma::store_matrix_sync(Cs + rt * 16 * CW + col_base + t * 16, acc[t], CW,
                                wmma::mem_row_major);
    __syncthreads();

    // Epilogue: smem fp32 -> global fp16 (buffers padded; unconditional writes)
#pragma unroll
    for (int j = tid; j < 64 * (N / 4); j += 256) {
        int r = j / (N / 4), c4 = j % (N / 4);
        float4 v = *(float4*)&Cs[r * CW + c4 * 4];
        if (EPI == 1) {
            float4 b = __ldg((const float4*)bias + c4);
            v.x = fmaxf(v.x + b.x, 0.f); v.y = fmaxf(v.y + b.y, 0.f);
            v.z = fmaxf(v.z + b.z, 0.f); v.w = fmaxf(v.w + b.w, 0.f);
            g_x1h[(size_t)(row0 + r) * 32 + c4] = pack_h4(v);
        } else {
            float sc = g_dinv[row0 + r];
            v.x *= sc; v.y *= sc; v.z *= sc; v.w *= sc;
            g_hs2h[(size_t)(row0 + r) * 16 + c4] = pack_h4(v);
        }
    }
}

extern "C" void kernel_launch(void* const* d_in, const int* in_sizes, int n_in,
                              void* d_out, int out_size) {
    const float* z   = (const float*)d_in[0];
    const int* ei    = (const int*)d_in[1];   // int32 OR int64 pairs (detected)
    const float* W1  = (const float*)d_in[2];
    const float* b1  = (const float*)d_in[3];
    const float* W2  = (const float*)d_in[4];
    const float* b2  = (const float*)d_in[5];
    float* out = (float*)d_out;

    void* cnt_ptr = nullptr;
    cudaGetSymbolAddress(&cnt_ptr, g_cnt);
    cudaMemsetAsync(cnt_ptr, 0, NN * sizeof(int));

    k_detect<<<1, 256>>>(ei);
    k_hist<<<(NE / 4 + 255) / 256, 256>>>(ei);
    k_scan1<<<SCAN_NB, SCAN_B>>>();
    k_prep<<<NN * 16 / 512, 256>>>((const float4*)z);
    k_permute<<<(NE / 4 + 255) / 256, 256>>>(ei);
    k_gather<true><<<NN * 16 / 256, 256>>>(nullptr, nullptr);
    k_gemm_wmma<64, 128, 1><<<(NN + 63) / 64, 256>>>(W1, b1);
    k_gemm_wmma<128, 64, 2><<<(NN + 63) / 64, 256>>>(W2, nullptr);
    k_gather<false><<<NN * 16 / 256, 256>>>((float4*)out, (const float4*)b2);
}